// round 2
// baseline (speedup 1.0000x reference)
#include <cuda_runtime.h>
#include <math_constants.h>

// ContrastiveLoss: B=16384, C=500, D=512
// loss = mean(relu(d_pos - d_neg_min + 1.0)), dists = sqrt(max(f2+p2-2*f.pT, 1e-12))
//
// k_norms : row squared norms + label-dtype sniff (int32 vs int64)
// k_gemm  : tiled fp32 GEMM, fused per-row (min over negatives, pos value)
//           of (p2[c] - 2*dot)  [f2 constant per row -> added in finalize]
// k_final : combine splits, +f2, sqrt, relu, mean

#define BM 64
#define BN 64
#define BKK 32
#define NSPLIT 2
#define MAXB 16384
#define MAXC 512

__device__ float g_f2[MAXB];
__device__ float g_p2[MAXC];
__device__ float g_min[NSPLIT * MAXB];
__device__ float g_pos[NSPLIT * MAXB];
__device__ int   g_lab64;   // 1 if labels are int64, 0 if int32

// ---------------------------------------------------------------------------
__global__ void k_norms(const float* __restrict__ feat,
                        const float* __restrict__ proto,
                        const int* __restrict__ labels32,
                        int B, int C, int D) {
    // dtype sniff: int64 labels (<500) viewed as int32 give [v,0,v,0,...]
    if (blockIdx.x == 0 && threadIdx.x == 0) {
        int any_odd_nonzero = 0;
        for (int i = 0; i < 64; i++)
            if (labels32[2 * i + 1] != 0) any_odd_nonzero = 1;
        g_lab64 = any_odd_nonzero ? 0 : 1;
    }

    int gwarp = (blockIdx.x * blockDim.x + threadIdx.x) >> 5;
    int lane  = threadIdx.x & 31;
    if (gwarp >= B + C) return;
    const float* row = (gwarp < B) ? feat + (size_t)gwarp * D
                                   : proto + (size_t)(gwarp - B) * D;
    float s = 0.f;
    for (int i = lane * 4; i < D; i += 128) {
        float4 v = *reinterpret_cast<const float4*>(row + i);
        s += v.x * v.x + v.y * v.y + v.z * v.z + v.w * v.w;
    }
    #pragma unroll
    for (int o = 16; o; o >>= 1) s += __shfl_down_sync(0xffffffffu, s, o);
    if (lane == 0) {
        if (gwarp < B) g_f2[gwarp] = s;
        else           g_p2[gwarp - B] = s;
    }
}

// ---------------------------------------------------------------------------
// 64x64 block tile, BK=32, 256 threads, 4x4 register tile per thread.
// grid = (B/BM, NSPLIT); split covers 256 columns of C.
// ---------------------------------------------------------------------------
__global__ __launch_bounds__(256)
void k_gemm(const float* __restrict__ feat,
            const float* __restrict__ proto,
            const void* __restrict__ labels,
            int B, int C, int D) {
    __shared__ float As[BKK][BM];
    __shared__ float Bs[BKK][BN];
    __shared__ float p2s[BN];

    const int t     = threadIdx.x;
    const int tx    = t & 15;
    const int ty    = t >> 4;
    const int row0  = blockIdx.x * BM;
    const int split = blockIdx.y;
    const int cbeg  = split * 256;
    const int cend  = min(C, cbeg + 256);
    const int lab64 = g_lab64;

    int   lab[4];
    float runmin[4], runpos[4];
    #pragma unroll
    for (int i = 0; i < 4; i++) {
        int r = row0 + ty * 4 + i;
        lab[i] = lab64 ? (int)((const long long*)labels)[r]
                       : ((const int*)labels)[r];
        runmin[i] = CUDART_INF_F;
        runpos[i] = CUDART_INF_F;
    }

    const int lrow = t >> 3;
    const int lk4  = (t & 7) * 4;

    for (int c0 = cbeg; c0 < cend; c0 += BN) {
        if (t < BN) {
            int c = c0 + t;
            p2s[t] = (c < cend) ? g_p2[c] : CUDART_INF_F;
        }

        float acc[4][4];
        #pragma unroll
        for (int i = 0; i < 4; i++)
            #pragma unroll
            for (int j = 0; j < 4; j++) acc[i][j] = 0.f;

        for (int k0 = 0; k0 < D; k0 += BKK) {
            __syncthreads();
            {
                float4 a0 = *reinterpret_cast<const float4*>(
                    feat + (size_t)(row0 + lrow) * D + k0 + lk4);
                float4 a1 = *reinterpret_cast<const float4*>(
                    feat + (size_t)(row0 + lrow + 32) * D + k0 + lk4);
                As[lk4 + 0][lrow] = a0.x;  As[lk4 + 1][lrow] = a0.y;
                As[lk4 + 2][lrow] = a0.z;  As[lk4 + 3][lrow] = a0.w;
                As[lk4 + 0][lrow + 32] = a1.x;  As[lk4 + 1][lrow + 32] = a1.y;
                As[lk4 + 2][lrow + 32] = a1.z;  As[lk4 + 3][lrow + 32] = a1.w;
            }
            {
                int c1 = c0 + lrow;
                int c2 = c1 + 32;
                float4 b0 = make_float4(0.f, 0.f, 0.f, 0.f);
                float4 b1 = make_float4(0.f, 0.f, 0.f, 0.f);
                if (c1 < C) b0 = *reinterpret_cast<const float4*>(
                    proto + (size_t)c1 * D + k0 + lk4);
                if (c2 < C) b1 = *reinterpret_cast<const float4*>(
                    proto + (size_t)c2 * D + k0 + lk4);
                Bs[lk4 + 0][lrow] = b0.x;  Bs[lk4 + 1][lrow] = b0.y;
                Bs[lk4 + 2][lrow] = b0.z;  Bs[lk4 + 3][lrow] = b0.w;
                Bs[lk4 + 0][lrow + 32] = b1.x;  Bs[lk4 + 1][lrow + 32] = b1.y;
                Bs[lk4 + 2][lrow + 32] = b1.z;  Bs[lk4 + 3][lrow + 32] = b1.w;
            }
            __syncthreads();

            #pragma unroll
            for (int kk = 0; kk < BKK; kk++) {
                float4 a = *reinterpret_cast<const float4*>(&As[kk][ty * 4]);
                float4 b = *reinterpret_cast<const float4*>(&Bs[kk][tx * 4]);
                acc[0][0] += a.x * b.x; acc[0][1] += a.x * b.y;
                acc[0][2] += a.x * b.z; acc[0][3] += a.x * b.w;
                acc[1][0] += a.y * b.x; acc[1][1] += a.y * b.y;
                acc[1][2] += a.y * b.z; acc[1][3] += a.y * b.w;
                acc[2][0] += a.z * b.x; acc[2][1] += a.z * b.y;
                acc[2][2] += a.z * b.z; acc[2][3] += a.z * b.w;
                acc[3][0] += a.w * b.x; acc[3][1] += a.w * b.y;
                acc[3][2] += a.w * b.z; acc[3][3] += a.w * b.w;
            }
        }

        #pragma unroll
        for (int i = 0; i < 4; i++) {
            #pragma unroll
            for (int j = 0; j < 4; j++) {
                int c = c0 + tx * 4 + j;
                float val = p2s[tx * 4 + j] - 2.f * acc[i][j];
                if (c < cend) {
                    if (c == lab[i]) runpos[i] = val;
                    else             runmin[i] = fminf(runmin[i], val);
                }
            }
        }
        __syncthreads();
    }

    #pragma unroll
    for (int i = 0; i < 4; i++) {
        #pragma unroll
        for (int o = 8; o; o >>= 1) {
            runmin[i] = fminf(runmin[i], __shfl_down_sync(0xffffffffu, runmin[i], o));
            runpos[i] = fminf(runpos[i], __shfl_down_sync(0xffffffffu, runpos[i], o));
        }
    }
    if (tx == 0) {
        #pragma unroll
        for (int i = 0; i < 4; i++) {
            int r = row0 + ty * 4 + i;
            g_min[split * B + r] = runmin[i];
            g_pos[split * B + r] = runpos[i];
        }
    }
}

// ---------------------------------------------------------------------------
__global__ void k_final(int B, float* __restrict__ out) {
    __shared__ float red[1024];
    float s = 0.f;
    for (int b = threadIdx.x; b < B; b += 1024) {
        float f2 = g_f2[b];
        float mn = fminf(g_min[b], g_min[B + b]);
        float pv = fminf(g_pos[b], g_pos[B + b]);
        float dpos = sqrtf(fmaxf(f2 + pv, 1e-12f));
        float dneg = sqrtf(fmaxf(f2 + mn, 1e-12f));
        float l = dpos - dneg + 1.0f;
        s += fmaxf(l, 0.f);
    }
    red[threadIdx.x] = s;
    __syncthreads();
    #pragma unroll
    for (int o = 512; o; o >>= 1) {
        if (threadIdx.x < o) red[threadIdx.x] += red[threadIdx.x + o];
        __syncthreads();
    }
    if (threadIdx.x == 0) out[0] = red[0] / (float)B;
}

// ---------------------------------------------------------------------------
extern "C" void kernel_launch(void* const* d_in, const int* in_sizes, int n_in,
                              void* d_out, int out_size) {
    const float* feat   = (const float*)d_in[0];
    const float* proto  = (const float*)d_in[1];
    const void*  labels = d_in[2];
    float*       out    = (float*)d_out;

    int B = in_sizes[2];                 // 16384
    int D = in_sizes[0] / B;             // 512
    int C = in_sizes[1] / D;             // 500

    int warps  = B + C;
    int nblks0 = (warps * 32 + 255) / 256;
    k_norms<<<nblks0, 256>>>(feat, proto, (const int*)labels, B, C, D);

    dim3 grid(B / BM, NSPLIT);
    k_gemm<<<grid, 256>>>(feat, proto, labels, B, C, D);

    k_final<<<1, 1024>>>(B, out);
}

// round 4
// speedup vs baseline: 4.3299x; 4.3299x over previous
#include <cuda_runtime.h>
#include <math_constants.h>
#include <cstdint>

// ContrastiveLoss B=16384, C=500, D=512
// mma.sync tf32 (m16n8k8) pipelined GEMM + fused per-row min/pos epilogue.
// (tcgen05 is unavailable: harness PTX target is compute_103 without 'a'.)

#define BM 128
#define BN 128
#define BK 32
#define NSTAGE 3
#define LDA 36                 // padded smem row stride in floats
#define MAXB 16384
#define MAXC 512
#define NYMAX 4

__device__ float g_f2[MAXB];
__device__ float g_p2[MAXC];
__device__ float g_min[NYMAX * MAXB];
__device__ float g_pos[NYMAX * MAXB];
__device__ int   g_lab64;

// ------------------------------------------------------------------ helpers
__device__ __forceinline__ uint32_t smem_u32(const void* p) {
    uint32_t a;
    asm("{ .reg .u64 t; cvta.to.shared.u64 t, %1; cvt.u32.u64 %0, t; }"
        : "=r"(a) : "l"(p));
    return a;
}
#define CPA(dst, src) \
    asm volatile("cp.async.cg.shared.global [%0], [%1], 16;" :: "r"(dst), "l"(src))
#define CPA_COMMIT() asm volatile("cp.async.commit_group;" ::: "memory")
#define CPA_WAIT(n)  asm volatile("cp.async.wait_group %0;" :: "n"(n) : "memory")

__device__ __forceinline__ void mma8(float* d, const uint32_t* a,
                                     uint32_t b0, uint32_t b1) {
    asm volatile(
        "mma.sync.aligned.m16n8k8.row.col.f32.tf32.tf32.f32 "
        "{%0,%1,%2,%3},{%4,%5,%6,%7},{%8,%9},{%0,%1,%2,%3};"
        : "+f"(d[0]), "+f"(d[1]), "+f"(d[2]), "+f"(d[3])
        : "r"(a[0]), "r"(a[1]), "r"(a[2]), "r"(a[3]), "r"(b0), "r"(b1));
}

// ---------------------------------------------------------------------------
// Kernel 0: squared norms + label dtype sniff (int32 vs int64 view)
// ---------------------------------------------------------------------------
__global__ void k_norms(const float* __restrict__ feat,
                        const float* __restrict__ proto,
                        const int* __restrict__ labels32,
                        int B, int C, int D) {
    if (blockIdx.x == 0 && threadIdx.x == 0) {
        int any_odd = 0;
        for (int i = 0; i < 64; i++)
            if (labels32[2 * i + 1] != 0) any_odd = 1;
        g_lab64 = any_odd ? 0 : 1;
    }
    int gwarp = (blockIdx.x * blockDim.x + threadIdx.x) >> 5;
    int lane  = threadIdx.x & 31;
    if (gwarp >= B + C) return;
    const float* row = (gwarp < B) ? feat + (size_t)gwarp * D
                                   : proto + (size_t)(gwarp - B) * D;
    float s0 = 0.f, s1 = 0.f, s2 = 0.f, s3 = 0.f;
    for (int i = lane * 4; i < D; i += 512) {
        float4 v = *reinterpret_cast<const float4*>(row + i);
        s0 += v.x * v.x; s1 += v.y * v.y; s2 += v.z * v.z; s3 += v.w * v.w;
        if (i + 128 < D) {
            float4 u = *reinterpret_cast<const float4*>(row + i + 128);
            s0 += u.x * u.x; s1 += u.y * u.y; s2 += u.z * u.z; s3 += u.w * u.w;
        }
        if (i + 256 < D) {
            float4 u = *reinterpret_cast<const float4*>(row + i + 256);
            s0 += u.x * u.x; s1 += u.y * u.y; s2 += u.z * u.z; s3 += u.w * u.w;
        }
        if (i + 384 < D) {
            float4 u = *reinterpret_cast<const float4*>(row + i + 384);
            s0 += u.x * u.x; s1 += u.y * u.y; s2 += u.z * u.z; s3 += u.w * u.w;
        }
    }
    float s = (s0 + s1) + (s2 + s3);
    #pragma unroll
    for (int o = 16; o; o >>= 1) s += __shfl_down_sync(0xffffffffu, s, o);
    if (lane == 0) {
        if (gwarp < B) g_f2[gwarp] = s;
        else           g_p2[gwarp - B] = s;
    }
}

// ---------------------------------------------------------------------------
// Kernel 1: 128x128 block tile tf32 mma.sync GEMM, fused epilogue.
// grid = (B/128, ceil(C/128)), 256 threads.
// ---------------------------------------------------------------------------
__device__ __forceinline__ void load_stage(uint32_t a_u, uint32_t b_u,
                                           const float* __restrict__ feat,
                                           const float* __restrict__ proto,
                                           int row0, int c0, int k0,
                                           int C, int D) {
    const int t = threadIdx.x;
    #pragma unroll
    for (int j = 0; j < 4; j++) {
        int i = t + j * 256;          // 0..1023
        int r = i >> 3;
        int q = i & 7;                // float4 index within 32-float row
        uint32_t off = (uint32_t)(r * LDA + q * 4) * 4u;
        const float* srcA = feat + (size_t)(row0 + r) * D + k0 + q * 4;
        CPA(a_u + off, srcA);
        int c  = c0 + r;
        int cc = c < C ? c : C - 1;   // clamp; masked via p2s=+inf
        const float* srcB = proto + (size_t)cc * D + k0 + q * 4;
        CPA(b_u + off, srcB);
    }
}

__global__ __launch_bounds__(256, 2)
void k_gemm(const float* __restrict__ feat,
            const float* __restrict__ proto,
            const void* __restrict__ labels,
            int B, int C, int D) {
    extern __shared__ float sm[];
    float* As  = sm;                               // [NSTAGE][BM][LDA]
    float* Bs  = sm + NSTAGE * BM * LDA;
    float* p2s = Bs + NSTAGE * BM * LDA;           // [BN]
    float* sred = Bs;                              // overlay after MMA phase

    const int t    = threadIdx.x;
    const int lane = t & 31;
    const int w    = t >> 5;
    const int wy   = w & 3;            // 4 M-warps
    const int wx   = w >> 2;           // 2 N-warps
    const int mw   = wy * 32;
    const int nw   = wx * 64;
    const int row0 = blockIdx.x * BM;
    const int c0   = blockIdx.y * BN;
    const int rb   = lane >> 2;        // 0..7
    const int cq   = lane & 3;         // 0..3

    for (int i = t; i < BN; i += 256) {
        int c = c0 + i;
        p2s[i] = (c < C) ? g_p2[c] : CUDART_INF_F;
    }

    float acc[2][8][4];
    #pragma unroll
    for (int fm = 0; fm < 2; fm++)
        #pragma unroll
        for (int fn = 0; fn < 8; fn++)
            #pragma unroll
            for (int ci = 0; ci < 4; ci++) acc[fm][fn][ci] = 0.f;

    const uint32_t as_u = smem_u32(As);
    const uint32_t bs_u = smem_u32(Bs);
    const uint32_t stage_b = (uint32_t)(BM * LDA) * 4u;

    const int NK = D / BK;             // 16
    load_stage(as_u, bs_u, feat, proto, row0, c0, 0, C, D);
    CPA_COMMIT();
    load_stage(as_u + stage_b, bs_u + stage_b, feat, proto, row0, c0, BK, C, D);
    CPA_COMMIT();

    for (int s = 0; s < NK; s++) {
        CPA_WAIT(1);                   // stage s resident
        __syncthreads();               // everyone done with stage s-1's buffer
        if (s + 2 < NK) {
            int nb = (s + 2) % NSTAGE;
            load_stage(as_u + nb * stage_b, bs_u + nb * stage_b,
                       feat, proto, row0, c0, (s + 2) * BK, C, D);
        }
        CPA_COMMIT();

        const float* A  = As + (s % NSTAGE) * BM * LDA;
        const float* Bt = Bs + (s % NSTAGE) * BM * LDA;
        #pragma unroll
        for (int kq = 0; kq < 4; kq++) {
            uint32_t a[2][4];
            #pragma unroll
            for (int fm = 0; fm < 2; fm++) {
                const float* ap = A + (mw + fm * 16 + rb) * LDA + kq * 8 + cq;
                a[fm][0] = __float_as_uint(ap[0]);
                a[fm][1] = __float_as_uint(ap[8 * LDA]);
                a[fm][2] = __float_as_uint(ap[4]);
                a[fm][3] = __float_as_uint(ap[8 * LDA + 4]);
            }
            #pragma unroll
            for (int fn = 0; fn < 8; fn++) {
                const float* bp = Bt + (nw + fn * 8 + rb) * LDA + kq * 8 + cq;
                uint32_t b0 = __float_as_uint(bp[0]);
                uint32_t b1 = __float_as_uint(bp[4]);
                mma8(acc[0][fn], a[0], b0, b1);
                mma8(acc[1][fn], a[1], b0, b1);
            }
        }
    }
    __syncthreads();   // MMA phase done; Bs stage 0 may now be overlaid

    // ----- fused epilogue: val = p2[c] - 2*dot; per-row min/pos -----
    const int lab64 = g_lab64;
    int   labv[2][2];
    float rmin[2][2], rpos[2][2];
    #pragma unroll
    for (int fm = 0; fm < 2; fm++)
        #pragma unroll
        for (int h = 0; h < 2; h++) {
            int r = row0 + mw + fm * 16 + rb + h * 8;
            labv[fm][h] = lab64 ? (int)((const long long*)labels)[r]
                                : ((const int*)labels)[r];
            rmin[fm][h] = CUDART_INF_F;
            rpos[fm][h] = CUDART_INF_F;
        }

    #pragma unroll
    for (int fm = 0; fm < 2; fm++)
        #pragma unroll
        for (int fn = 0; fn < 8; fn++)
            #pragma unroll
            for (int ci = 0; ci < 4; ci++) {
                int h   = ci >> 1;
                int col = nw + fn * 8 + cq * 2 + (ci & 1);
                int c   = c0 + col;
                float val = p2s[col] - 2.f * acc[fm][fn][ci];
                if (c == labv[fm][h]) rpos[fm][h] = val;
                else                  rmin[fm][h] = fminf(rmin[fm][h], val);
            }

    // reduce across the 4 lanes of each quad (same rows)
    #pragma unroll
    for (int o = 1; o <= 2; o <<= 1)
        #pragma unroll
        for (int fm = 0; fm < 2; fm++)
            #pragma unroll
            for (int h = 0; h < 2; h++) {
                rmin[fm][h] = fminf(rmin[fm][h],
                                    __shfl_xor_sync(0xffffffffu, rmin[fm][h], o));
                rpos[fm][h] = fminf(rpos[fm][h],
                                    __shfl_xor_sync(0xffffffffu, rpos[fm][h], o));
            }

    if (cq == 0) {
        #pragma unroll
        for (int fm = 0; fm < 2; fm++)
            #pragma unroll
            for (int h = 0; h < 2; h++) {
                int r = mw + fm * 16 + rb + h * 8;   // 0..127
                sred[wx * BM + r]            = rmin[fm][h];
                sred[2 * BM + wx * BM + r]   = rpos[fm][h];
            }
    }
    __syncthreads();

    if (t < BM) {
        float m = fminf(sred[t], sred[BM + t]);
        float p = fminf(sred[2 * BM + t], sred[3 * BM + t]);
        g_min[blockIdx.y * B + row0 + t] = m;
        g_pos[blockIdx.y * B + row0 + t] = p;
    }
}

// ---------------------------------------------------------------------------
__global__ void k_final(int B, int NY, float* __restrict__ out) {
    __shared__ float red[1024];
    float s = 0.f;
    for (int i = threadIdx.x; i < B; i += 1024) {
        float mn = CUDART_INF_F, pv = CUDART_INF_F;
        for (int y = 0; y < NY; y++) {
            mn = fminf(mn, g_min[y * B + i]);
            pv = fminf(pv, g_pos[y * B + i]);
        }
        float f2 = g_f2[i];
        float dpos = sqrtf(fmaxf(f2 + pv, 1e-12f));
        float dneg = sqrtf(fmaxf(f2 + mn, 1e-12f));
        s += fmaxf(dpos - dneg + 1.0f, 0.f);
    }
    red[threadIdx.x] = s;
    __syncthreads();
    #pragma unroll
    for (int o = 512; o; o >>= 1) {
        if (threadIdx.x < o) red[threadIdx.x] += red[threadIdx.x + o];
        __syncthreads();
    }
    if (threadIdx.x == 0) out[0] = red[0] / (float)B;
}

// ---------------------------------------------------------------------------
extern "C" void kernel_launch(void* const* d_in, const int* in_sizes, int n_in,
                              void* d_out, int out_size) {
    const float* feat   = (const float*)d_in[0];
    const float* proto  = (const float*)d_in[1];
    const void*  labels = d_in[2];
    float*       out    = (float*)d_out;

    int B = in_sizes[2];                 // 16384
    int D = in_sizes[0] / B;             // 512
    int C = in_sizes[1] / D;             // 500
    int NY = (C + BN - 1) / BN;          // 4

    static int smem_set = 0;
    int smem_bytes = (2 * NSTAGE * BM * LDA + BN) * 4;
    if (!smem_set) {
        cudaFuncSetAttribute(k_gemm, cudaFuncAttributeMaxDynamicSharedMemorySize,
                             smem_bytes);
        smem_set = 1;
    }

    int warps  = B + C;
    int nblks0 = (warps * 32 + 255) / 256;
    k_norms<<<nblks0, 256>>>(feat, proto, (const int*)labels, B, C, D);

    dim3 grid(B / BM, NY);
    k_gemm<<<grid, 256, smem_bytes>>>(feat, proto, labels, B, C, D);

    k_final<<<1, 1024>>>(B, NY, out);
}

// round 5
// speedup vs baseline: 4.8798x; 1.1270x over previous
#include <cuda_runtime.h>
#include <math_constants.h>
#include <cstdint>

// ContrastiveLoss B=16384, C=500, D=512
// mma.sync tf32 (m16n8k8) pipelined GEMM, ldmatrix fragments, fully fused:
// p2/f2 norms computed from resident smem tiles; k_norms eliminated.

#define BM 128
#define BN 128
#define BK 32
#define NSTAGE 3
#define LDA 36                 // padded smem row stride (floats)
#define MAXB 16384
#define NYMAX 4

__device__ float g_f2[MAXB];
__device__ float g_min[NYMAX * MAXB];
__device__ float g_pos[NYMAX * MAXB];

// ------------------------------------------------------------------ helpers
__device__ __forceinline__ uint32_t smem_u32(const void* p) {
    uint32_t a;
    asm("{ .reg .u64 t; cvta.to.shared.u64 t, %1; cvt.u32.u64 %0, t; }"
        : "=r"(a) : "l"(p));
    return a;
}
#define CPA(dst, src) \
    asm volatile("cp.async.cg.shared.global [%0], [%1], 16;" :: "r"(dst), "l"(src))
#define CPA_COMMIT() asm volatile("cp.async.commit_group;" ::: "memory")
#define CPA_WAIT(n)  asm volatile("cp.async.wait_group %0;" :: "n"(n) : "memory")

#define LDSM4(r0, r1, r2, r3, a) \
    asm volatile("ldmatrix.sync.aligned.m8n8.x4.shared.b16 {%0,%1,%2,%3}, [%4];" \
        : "=r"(r0), "=r"(r1), "=r"(r2), "=r"(r3) : "r"(a))

__device__ __forceinline__ void mma8(float* d, const uint32_t* a,
                                     uint32_t b0, uint32_t b1) {
    asm volatile(
        "mma.sync.aligned.m16n8k8.row.col.f32.tf32.tf32.f32 "
        "{%0,%1,%2,%3},{%4,%5,%6,%7},{%8,%9},{%0,%1,%2,%3};"
        : "+f"(d[0]), "+f"(d[1]), "+f"(d[2]), "+f"(d[3])
        : "r"(a[0]), "r"(a[1]), "r"(a[2]), "r"(a[3]), "r"(b0), "r"(b1));
}

// ---------------------------------------------------------------------------
// k_gemm: 128x128 block tile, BK=32, 3-stage cp.async, 256 threads.
// grid = (B/128, ceil(C/128)). Fused: p2 per-CTA, f2 by y==0 CTAs,
// label dtype sniff per-CTA, per-row min/pos epilogue.
// ---------------------------------------------------------------------------
__device__ __forceinline__ void load_stage(uint32_t a_u, uint32_t b_u,
                                           const float* __restrict__ feat,
                                           const float* __restrict__ proto,
                                           int row0, int c0, int k0,
                                           int C, int D) {
    const int t = threadIdx.x;
    #pragma unroll
    for (int j = 0; j < 4; j++) {
        int i = t + j * 256;          // 0..1023
        int r = i >> 3;
        int q = i & 7;
        uint32_t off = (uint32_t)(r * LDA + q * 4) * 4u;
        const float* srcA = feat + (size_t)(row0 + r) * D + k0 + q * 4;
        CPA(a_u + off, srcA);
        int c  = c0 + r;
        int cc = c < C ? c : C - 1;   // clamp; masked via p2s=+inf
        const float* srcB = proto + (size_t)cc * D + k0 + q * 4;
        CPA(b_u + off, srcB);
    }
}

__global__ __launch_bounds__(256, 2)
void k_gemm(const float* __restrict__ feat,
            const float* __restrict__ proto,
            const void* __restrict__ labels,
            int B, int C, int D) {
    extern __shared__ float sm[];
    float* As   = sm;                              // [NSTAGE][BM][LDA]
    float* Bs   = sm + NSTAGE * BM * LDA;
    float* p2s  = Bs + NSTAGE * BM * LDA;          // [BN]
    int*   sfl  = (int*)(p2s + BN);
    float* sred = Bs;                              // overlay after MMA phase

    const int t    = threadIdx.x;
    const int lane = t & 31;
    const int w    = t >> 5;
    const int wy   = w & 3;            // 4 M-warps
    const int wx   = w >> 2;           // 2 N-warps
    const int mw   = wy * 32;
    const int nw   = wx * 64;
    const int row0 = blockIdx.x * BM;
    const int c0   = blockIdx.y * BN;
    const int rb   = lane >> 2;
    const int cq   = lane & 3;

    // label dtype sniff: odd int32 words of the first 64 ints (in-bounds for
    // either dtype). int64 labels (<500) viewed as int32 have zero odd words.
    if (t < 32) {
        unsigned bal = __ballot_sync(0xffffffffu,
                                     ((const int*)labels)[2 * lane + 1] != 0);
        if (lane == 0) sfl[0] = (bal == 0) ? 1 : 0;
    }

    float acc[2][8][4];
    #pragma unroll
    for (int fm = 0; fm < 2; fm++)
        #pragma unroll
        for (int fn = 0; fn < 8; fn++)
            #pragma unroll
            for (int ci = 0; ci < 4; ci++) acc[fm][fn][ci] = 0.f;

    const uint32_t as_u    = smem_u32(As);
    const uint32_t bs_u    = smem_u32(Bs);
    const uint32_t stage_b = (uint32_t)(BM * LDA) * 4u;

    // ldmatrix per-thread byte offsets
    const uint32_t a_off = ((uint32_t)(mw + (lane & 15)) * LDA
                            + ((lane >> 4) << 2)) * 4u;
    const uint32_t b_off = ((uint32_t)(nw + (lane & 7) + (((lane >> 4) & 1) << 3)) * LDA
                            + (((lane >> 3) & 1) << 2)) * 4u;

    const int NK = D / BK;             // 16
    load_stage(as_u, bs_u, feat, proto, row0, c0, 0, C, D);
    CPA_COMMIT();
    load_stage(as_u + stage_b, bs_u + stage_b, feat, proto, row0, c0, BK, C, D);
    CPA_COMMIT();

    // fused norm accumulators: thread pair (t, t^1) shares row t>>1
    float pnorm = 0.f, anorm = 0.f;
    const int  nr   = t >> 1;
    const int  ncol = (t & 1) * 16;
    const bool do_a = (blockIdx.y == 0);

    for (int s = 0; s < NK; s++) {
        CPA_WAIT(1);
        __syncthreads();
        if (s + 2 < NK) {
            int nb = (s + 2) % NSTAGE;
            load_stage(as_u + nb * stage_b, bs_u + nb * stage_b,
                       feat, proto, row0, c0, (s + 2) * BK, C, D);
        }
        CPA_COMMIT();

        const int buf = s % NSTAGE;
        // norms from resident tiles
        {
            const float* br = Bs + buf * BM * LDA + nr * LDA + ncol;
            #pragma unroll
            for (int j = 0; j < 4; j++) {
                float4 v = *reinterpret_cast<const float4*>(br + j * 4);
                pnorm += v.x * v.x + v.y * v.y + v.z * v.z + v.w * v.w;
            }
            if (do_a) {
                const float* ar = As + buf * BM * LDA + nr * LDA + ncol;
                #pragma unroll
                for (int j = 0; j < 4; j++) {
                    float4 v = *reinterpret_cast<const float4*>(ar + j * 4);
                    anorm += v.x * v.x + v.y * v.y + v.z * v.z + v.w * v.w;
                }
            }
        }

        const uint32_t abase = as_u + buf * stage_b;
        const uint32_t bbase = bs_u + buf * stage_b;
        #pragma unroll
        for (int kq = 0; kq < 4; kq++) {
            uint32_t a[2][4], b[4][4];
            LDSM4(a[0][0], a[0][1], a[0][2], a[0][3],
                  abase + a_off + kq * 32);
            LDSM4(a[1][0], a[1][1], a[1][2], a[1][3],
                  abase + a_off + 16u * LDA * 4u + kq * 32);
            #pragma unroll
            for (int fp = 0; fp < 4; fp++)
                LDSM4(b[fp][0], b[fp][1], b[fp][2], b[fp][3],
                      bbase + b_off + (uint32_t)fp * 16u * LDA * 4u + kq * 32);
            #pragma unroll
            for (int fp = 0; fp < 4; fp++) {
                mma8(acc[0][2 * fp],     a[0], b[fp][0], b[fp][1]);
                mma8(acc[0][2 * fp + 1], a[0], b[fp][2], b[fp][3]);
                mma8(acc[1][2 * fp],     a[1], b[fp][0], b[fp][1]);
                mma8(acc[1][2 * fp + 1], a[1], b[fp][2], b[fp][3]);
            }
        }
    }
    __syncthreads();

    // finalize norms
    pnorm += __shfl_xor_sync(0xffffffffu, pnorm, 1);
    if (do_a) anorm += __shfl_xor_sync(0xffffffffu, anorm, 1);
    if ((t & 1) == 0) {
        p2s[nr] = (c0 + nr < C) ? pnorm : CUDART_INF_F;
        if (do_a) g_f2[row0 + nr] = anorm;
    }
    __syncthreads();

    // ----- fused epilogue: val = p2[c] - 2*dot; per-row min/pos -----
    const int lab64 = sfl[0];
    int   labv[2][2];
    float rmin[2][2], rpos[2][2];
    #pragma unroll
    for (int fm = 0; fm < 2; fm++)
        #pragma unroll
        for (int h = 0; h < 2; h++) {
            int r = row0 + mw + fm * 16 + rb + h * 8;
            labv[fm][h] = lab64 ? (int)((const long long*)labels)[r]
                                : ((const int*)labels)[r];
            rmin[fm][h] = CUDART_INF_F;
            rpos[fm][h] = CUDART_INF_F;
        }

    #pragma unroll
    for (int fm = 0; fm < 2; fm++)
        #pragma unroll
        for (int fn = 0; fn < 8; fn++)
            #pragma unroll
            for (int ci = 0; ci < 4; ci++) {
                int h   = ci >> 1;
                int col = nw + fn * 8 + cq * 2 + (ci & 1);
                int c   = c0 + col;
                float val = p2s[col] - 2.f * acc[fm][fn][ci];
                if (c == labv[fm][h]) rpos[fm][h] = val;
                else                  rmin[fm][h] = fminf(rmin[fm][h], val);
            }

    #pragma unroll
    for (int o = 1; o <= 2; o <<= 1)
        #pragma unroll
        for (int fm = 0; fm < 2; fm++)
            #pragma unroll
            for (int h = 0; h < 2; h++) {
                rmin[fm][h] = fminf(rmin[fm][h],
                                    __shfl_xor_sync(0xffffffffu, rmin[fm][h], o));
                rpos[fm][h] = fminf(rpos[fm][h],
                                    __shfl_xor_sync(0xffffffffu, rpos[fm][h], o));
            }

    if (cq == 0) {
        #pragma unroll
        for (int fm = 0; fm < 2; fm++)
            #pragma unroll
            for (int h = 0; h < 2; h++) {
                int r = mw + fm * 16 + rb + h * 8;   // 0..127
                sred[wx * BM + r]          = rmin[fm][h];
                sred[2 * BM + wx * BM + r] = rpos[fm][h];
            }
    }
    __syncthreads();

    if (t < BM) {
        float m = fminf(sred[t], sred[BM + t]);
        float p = fminf(sred[2 * BM + t], sred[3 * BM + t]);
        g_min[blockIdx.y * B + row0 + t] = m;
        g_pos[blockIdx.y * B + row0 + t] = p;
    }
}

// ---------------------------------------------------------------------------
__global__ void k_final(int B, int NY, float* __restrict__ out) {
    __shared__ float red[1024];
    float s = 0.f;
    for (int i = threadIdx.x; i < B; i += 1024) {
        float mn = CUDART_INF_F, pv = CUDART_INF_F;
        for (int y = 0; y < NY; y++) {
            mn = fminf(mn, g_min[y * B + i]);
            pv = fminf(pv, g_pos[y * B + i]);
        }
        float f2 = g_f2[i];
        float dpos = sqrtf(fmaxf(f2 + pv, 1e-12f));
        float dneg = sqrtf(fmaxf(f2 + mn, 1e-12f));
        s += fmaxf(dpos - dneg + 1.0f, 0.f);
    }
    red[threadIdx.x] = s;
    __syncthreads();
    #pragma unroll
    for (int o = 512; o; o >>= 1) {
        if (threadIdx.x < o) red[threadIdx.x] += red[threadIdx.x + o];
        __syncthreads();
    }
    if (threadIdx.x == 0) out[0] = red[0] / (float)B;
}

// ---------------------------------------------------------------------------
extern "C" void kernel_launch(void* const* d_in, const int* in_sizes, int n_in,
                              void* d_out, int out_size) {
    const float* feat   = (const float*)d_in[0];
    const float* proto  = (const float*)d_in[1];
    const void*  labels = d_in[2];
    float*       out    = (float*)d_out;

    int B = in_sizes[2];                 // 16384
    int D = in_sizes[0] / B;             // 512
    int C = in_sizes[1] / D;             // 500
    int NY = (C + BN - 1) / BN;          // 4

    int smem_bytes = (2 * NSTAGE * BM * LDA + BN) * 4 + 16;
    static int smem_set = 0;
    if (!smem_set) {
        cudaFuncSetAttribute(k_gemm, cudaFuncAttributeMaxDynamicSharedMemorySize,
                             smem_bytes);
        smem_set = 1;
    }

    dim3 grid(B / BM, NY);
    k_gemm<<<grid, 256, smem_bytes>>>(feat, proto, labels, B, C, D);

    k_final<<<1, 1024>>>(B, NY, out);
}

// round 6
// speedup vs baseline: 5.6178x; 1.1512x over previous
#include <cuda_runtime.h>
#include <math_constants.h>
#include <cstdint>

// ContrastiveLoss B=16384, C=500, D=512
// mma.sync tf32 (m16n8k8) pipelined GEMM, ldmatrix fragments, fully fused
// norms; parallel grid-wide finalize (atomicAdd into out).

#define BM 128
#define BN 128
#define BK 32
#define NSTAGE 3
#define LDA 36                 // padded smem row stride (floats)
#define MAXB 16384
#define NYMAX 4

__device__ float g_f2[MAXB];
__device__ float g_min[NYMAX * MAXB];
__device__ float g_pos[NYMAX * MAXB];

// ------------------------------------------------------------------ helpers
__device__ __forceinline__ uint32_t smem_u32(const void* p) {
    uint32_t a;
    asm("{ .reg .u64 t; cvta.to.shared.u64 t, %1; cvt.u32.u64 %0, t; }"
        : "=r"(a) : "l"(p));
    return a;
}
#define CPA(dst, src) \
    asm volatile("cp.async.cg.shared.global [%0], [%1], 16;" :: "r"(dst), "l"(src))
#define CPA_COMMIT() asm volatile("cp.async.commit_group;" ::: "memory")
#define CPA_WAIT(n)  asm volatile("cp.async.wait_group %0;" :: "n"(n) : "memory")

#define LDSM4(r0, r1, r2, r3, a) \
    asm volatile("ldmatrix.sync.aligned.m8n8.x4.shared.b16 {%0,%1,%2,%3}, [%4];" \
        : "=r"(r0), "=r"(r1), "=r"(r2), "=r"(r3) : "r"(a))

__device__ __forceinline__ void mma8(float* d, const uint32_t* a,
                                     uint32_t b0, uint32_t b1) {
    asm volatile(
        "mma.sync.aligned.m16n8k8.row.col.f32.tf32.tf32.f32 "
        "{%0,%1,%2,%3},{%4,%5,%6,%7},{%8,%9},{%0,%1,%2,%3};"
        : "+f"(d[0]), "+f"(d[1]), "+f"(d[2]), "+f"(d[3])
        : "r"(a[0]), "r"(a[1]), "r"(a[2]), "r"(a[3]), "r"(b0), "r"(b1));
}

// ---------------------------------------------------------------------------
// k_gemm: 128x128 block tile, BK=32, 3-stage cp.async, 256 threads.
// grid = (B/128, ceil(C/128)). Fused: p2 per-CTA, f2 by y==0 CTAs,
// label dtype sniff per-CTA, per-row min/pos epilogue.
// ---------------------------------------------------------------------------
__device__ __forceinline__ void load_stage(uint32_t a_u, uint32_t b_u,
                                           const float* __restrict__ feat,
                                           const float* __restrict__ proto,
                                           int row0, int c0, int k0,
                                           int C, int D) {
    const int t = threadIdx.x;
    #pragma unroll
    for (int j = 0; j < 4; j++) {
        int i = t + j * 256;          // 0..1023
        int r = i >> 3;
        int q = i & 7;
        uint32_t off = (uint32_t)(r * LDA + q * 4) * 4u;
        const float* srcA = feat + (size_t)(row0 + r) * D + k0 + q * 4;
        CPA(a_u + off, srcA);
        int c  = c0 + r;
        int cc = c < C ? c : C - 1;   // clamp; masked via p2s=+inf
        const float* srcB = proto + (size_t)cc * D + k0 + q * 4;
        CPA(b_u + off, srcB);
    }
}

__global__ __launch_bounds__(256, 2)
void k_gemm(const float* __restrict__ feat,
            const float* __restrict__ proto,
            const void* __restrict__ labels,
            int B, int C, int D) {
    extern __shared__ float sm[];
    float* As   = sm;                              // [NSTAGE][BM][LDA]
    float* Bs   = sm + NSTAGE * BM * LDA;
    float* p2s  = Bs + NSTAGE * BM * LDA;          // [BN]
    int*   sfl  = (int*)(p2s + BN);
    float* sred = Bs;                              // overlay after MMA phase

    const int t    = threadIdx.x;
    const int lane = t & 31;
    const int w    = t >> 5;
    const int wy   = w & 3;            // 4 M-warps
    const int wx   = w >> 2;           // 2 N-warps
    const int mw   = wy * 32;
    const int nw   = wx * 64;
    const int row0 = blockIdx.x * BM;
    const int c0   = blockIdx.y * BN;
    const int rb   = lane >> 2;
    const int cq   = lane & 3;

    // label dtype sniff: odd int32 words of the first 64 ints (in-bounds for
    // either dtype). int64 labels (<500) viewed as int32 have zero odd words.
    if (t < 32) {
        unsigned bal = __ballot_sync(0xffffffffu,
                                     ((const int*)labels)[2 * lane + 1] != 0);
        if (lane == 0) sfl[0] = (bal == 0) ? 1 : 0;
    }

    float acc[2][8][4];
    #pragma unroll
    for (int fm = 0; fm < 2; fm++)
        #pragma unroll
        for (int fn = 0; fn < 8; fn++)
            #pragma unroll
            for (int ci = 0; ci < 4; ci++) acc[fm][fn][ci] = 0.f;

    const uint32_t as_u    = smem_u32(As);
    const uint32_t bs_u    = smem_u32(Bs);
    const uint32_t stage_b = (uint32_t)(BM * LDA) * 4u;

    // ldmatrix per-thread byte offsets
    const uint32_t a_off = ((uint32_t)(mw + (lane & 15)) * LDA
                            + ((lane >> 4) << 2)) * 4u;
    const uint32_t b_off = ((uint32_t)(nw + (lane & 7) + (((lane >> 4) & 1) << 3)) * LDA
                            + (((lane >> 3) & 1) << 2)) * 4u;

    const int NK = D / BK;             // 16
    load_stage(as_u, bs_u, feat, proto, row0, c0, 0, C, D);
    CPA_COMMIT();
    load_stage(as_u + stage_b, bs_u + stage_b, feat, proto, row0, c0, BK, C, D);
    CPA_COMMIT();

    // fused norm accumulators: thread pair (t, t^1) shares row t>>1
    float pnorm = 0.f, anorm = 0.f;
    const int  nr   = t >> 1;
    const int  ncol = (t & 1) * 16;
    const bool do_a = (blockIdx.y == 0);

    for (int s = 0; s < NK; s++) {
        CPA_WAIT(1);
        __syncthreads();
        if (s + 2 < NK) {
            int nb = (s + 2) % NSTAGE;
            load_stage(as_u + nb * stage_b, bs_u + nb * stage_b,
                       feat, proto, row0, c0, (s + 2) * BK, C, D);
        }
        CPA_COMMIT();

        const int buf = s % NSTAGE;
        // norms from resident tiles
        {
            const float* br = Bs + buf * BM * LDA + nr * LDA + ncol;
            #pragma unroll
            for (int j = 0; j < 4; j++) {
                float4 v = *reinterpret_cast<const float4*>(br + j * 4);
                pnorm += v.x * v.x + v.y * v.y + v.z * v.z + v.w * v.w;
            }
            if (do_a) {
                const float* ar = As + buf * BM * LDA + nr * LDA + ncol;
                #pragma unroll
                for (int j = 0; j < 4; j++) {
                    float4 v = *reinterpret_cast<const float4*>(ar + j * 4);
                    anorm += v.x * v.x + v.y * v.y + v.z * v.z + v.w * v.w;
                }
            }
        }

        const uint32_t abase = as_u + buf * stage_b;
        const uint32_t bbase = bs_u + buf * stage_b;
        #pragma unroll
        for (int kq = 0; kq < 4; kq++) {
            uint32_t a[2][4], b[4][4];
            LDSM4(a[0][0], a[0][1], a[0][2], a[0][3],
                  abase + a_off + kq * 32);
            LDSM4(a[1][0], a[1][1], a[1][2], a[1][3],
                  abase + a_off + 16u * LDA * 4u + kq * 32);
            #pragma unroll
            for (int fp = 0; fp < 4; fp++)
                LDSM4(b[fp][0], b[fp][1], b[fp][2], b[fp][3],
                      bbase + b_off + (uint32_t)fp * 16u * LDA * 4u + kq * 32);
            #pragma unroll
            for (int fp = 0; fp < 4; fp++) {
                mma8(acc[0][2 * fp],     a[0], b[fp][0], b[fp][1]);
                mma8(acc[0][2 * fp + 1], a[0], b[fp][2], b[fp][3]);
                mma8(acc[1][2 * fp],     a[1], b[fp][0], b[fp][1]);
                mma8(acc[1][2 * fp + 1], a[1], b[fp][2], b[fp][3]);
            }
        }
    }
    __syncthreads();

    // finalize norms
    pnorm += __shfl_xor_sync(0xffffffffu, pnorm, 1);
    if (do_a) anorm += __shfl_xor_sync(0xffffffffu, anorm, 1);
    if ((t & 1) == 0) {
        p2s[nr] = (c0 + nr < C) ? pnorm : CUDART_INF_F;
        if (do_a) g_f2[row0 + nr] = anorm;
    }
    __syncthreads();

    // ----- fused epilogue: val = p2[c] - 2*dot; per-row min/pos -----
    const int lab64 = sfl[0];
    int   labv[2][2];
    float rmin[2][2], rpos[2][2];
    #pragma unroll
    for (int fm = 0; fm < 2; fm++)
        #pragma unroll
        for (int h = 0; h < 2; h++) {
            int r = row0 + mw + fm * 16 + rb + h * 8;
            labv[fm][h] = lab64 ? (int)((const long long*)labels)[r]
                                : ((const int*)labels)[r];
            rmin[fm][h] = CUDART_INF_F;
            rpos[fm][h] = CUDART_INF_F;
        }

    #pragma unroll
    for (int fm = 0; fm < 2; fm++)
        #pragma unroll
        for (int fn = 0; fn < 8; fn++)
            #pragma unroll
            for (int ci = 0; ci < 4; ci++) {
                int h   = ci >> 1;
                int col = nw + fn * 8 + cq * 2 + (ci & 1);
                int c   = c0 + col;
                float val = p2s[col] - 2.f * acc[fm][fn][ci];
                if (c == labv[fm][h]) rpos[fm][h] = val;
                else                  rmin[fm][h] = fminf(rmin[fm][h], val);
            }

    #pragma unroll
    for (int o = 1; o <= 2; o <<= 1)
        #pragma unroll
        for (int fm = 0; fm < 2; fm++)
            #pragma unroll
            for (int h = 0; h < 2; h++) {
                rmin[fm][h] = fminf(rmin[fm][h],
                                    __shfl_xor_sync(0xffffffffu, rmin[fm][h], o));
                rpos[fm][h] = fminf(rpos[fm][h],
                                    __shfl_xor_sync(0xffffffffu, rpos[fm][h], o));
            }

    if (cq == 0) {
        #pragma unroll
        for (int fm = 0; fm < 2; fm++)
            #pragma unroll
            for (int h = 0; h < 2; h++) {
                int r = mw + fm * 16 + rb + h * 8;   // 0..127
                sred[wx * BM + r]          = rmin[fm][h];
                sred[2 * BM + wx * BM + r] = rpos[fm][h];
            }
    }
    __syncthreads();

    if (t < BM) {
        float m = fminf(sred[t], sred[BM + t]);
        float p = fminf(sred[2 * BM + t], sred[3 * BM + t]);
        g_min[blockIdx.y * B + row0 + t] = m;
        g_pos[blockIdx.y * B + row0 + t] = p;
    }
}

// ---------------------------------------------------------------------------
// k_final: grid-parallel. Each CTA reduces a slice of rows, one atomicAdd.
// out[0] must be zeroed before launch (cudaMemsetAsync in kernel_launch).
// ---------------------------------------------------------------------------
__global__ void k_final(int B, int NY, float* __restrict__ out) {
    __shared__ float red[256];
    const float invB = 1.0f / (float)B;
    float s = 0.f;
    for (int i = blockIdx.x * blockDim.x + threadIdx.x; i < B;
         i += gridDim.x * blockDim.x) {
        float mn = CUDART_INF_F, pv = CUDART_INF_F;
        #pragma unroll
        for (int y = 0; y < NYMAX; y++) {
            if (y < NY) {
                mn = fminf(mn, g_min[y * B + i]);
                pv = fminf(pv, g_pos[y * B + i]);
            }
        }
        float f2 = g_f2[i];
        float dpos = sqrtf(fmaxf(f2 + pv, 1e-12f));
        float dneg = sqrtf(fmaxf(f2 + mn, 1e-12f));
        s += fmaxf(dpos - dneg + 1.0f, 0.f);
    }
    red[threadIdx.x] = s;
    __syncthreads();
    #pragma unroll
    for (int o = 128; o; o >>= 1) {
        if (threadIdx.x < o) red[threadIdx.x] += red[threadIdx.x + o];
        __syncthreads();
    }
    if (threadIdx.x == 0) atomicAdd(out, red[0] * invB);
}

// ---------------------------------------------------------------------------
extern "C" void kernel_launch(void* const* d_in, const int* in_sizes, int n_in,
                              void* d_out, int out_size) {
    const float* feat   = (const float*)d_in[0];
    const float* proto  = (const float*)d_in[1];
    const void*  labels = d_in[2];
    float*       out    = (float*)d_out;

    int B = in_sizes[2];                 // 16384
    int D = in_sizes[0] / B;             // 512
    int C = in_sizes[1] / D;             // 500
    int NY = (C + BN - 1) / BN;          // 4

    int smem_bytes = (2 * NSTAGE * BM * LDA + BN) * 4 + 16;
    static int smem_set = 0;
    if (!smem_set) {
        cudaFuncSetAttribute(k_gemm, cudaFuncAttributeMaxDynamicSharedMemorySize,
                             smem_bytes);
        smem_set = 1;
    }

    dim3 grid(B / BM, NY);
    k_gemm<<<grid, 256, smem_bytes>>>(feat, proto, labels, B, C, D);

    cudaMemsetAsync(out, 0, sizeof(float));
    k_final<<<128, 256>>>(B, NY, out);
}